// round 16
// baseline (speedup 1.0000x reference)
#include <cuda_runtime.h>
#include <cuda_bf16.h>
#include <cuda_fp16.h>
#include <math.h>
#include <stdint.h>

#define NN 50000
#define EE 100000
#define HH 768
#define NHD 12
#define HDD 64
#define NGR 64
#define NCL 10
#define H2 384

// ---------------- scratch (static device globals; no allocation) ----------------
__device__ float g_bufA[(size_t)NN * HH];
__device__ __half g_bufB[(size_t)NN * HH];
__device__ __half g_Ah[(size_t)NN * HH];
__device__ __half g_W4[4][(size_t)HH * HH];   // transposed: [N=768][K=768]
__device__ float g_dinv[NN];
__device__ int   g_cnt[NN];
__device__ int   g_rowstart[NN + 1];
__device__ int   g_cursor[NN];
__device__ int   g_csrsrc[EE];
__device__ float g_as[NN * NHD];
__device__ float g_ad[NN * NHD];
__device__ float g_pool[NGR * HH];
__device__ float g_zmlp[NGR * H2];

__device__ __forceinline__ float lrelu(float x) { return x > 0.f ? x : 0.2f * x; }

// ---------------- CSR build ----------------
__global__ void k_zero_cnt() {
    int i = blockIdx.x * blockDim.x + threadIdx.x;
    if (i < NN) g_cnt[i] = 0;
}

__global__ void k_count(const int* __restrict__ ei) {
    int e = blockIdx.x * blockDim.x + threadIdx.x;
    if (e < EE) atomicAdd(&g_cnt[ei[EE + e]], 1);
}

__global__ void k_scan() {
    __shared__ int sh[1024];
    int tid = threadIdx.x;
    int off = 0;
    for (int base = 0; base < NN; base += 1024) {
        int i = base + tid;
        int v = (i < NN) ? g_cnt[i] : 0;
        sh[tid] = v;
        __syncthreads();
        for (int s = 1; s < 1024; s <<= 1) {
            int t = (tid >= s) ? sh[tid - s] : 0;
            __syncthreads();
            sh[tid] += t;
            __syncthreads();
        }
        if (i < NN) {
            int excl = off + sh[tid] - v;
            g_rowstart[i] = excl;
            g_cursor[i] = excl;
        }
        int tot = sh[1023];
        __syncthreads();
        off += tot;
    }
    if (tid == 0) g_rowstart[NN] = off;
}

__global__ void k_dinv() {
    int i = blockIdx.x * blockDim.x + threadIdx.x;
    if (i < NN) g_dinv[i] = rsqrtf((float)(g_cnt[i] + 1));
}

__global__ void k_fill(const int* __restrict__ ei) {
    int e = blockIdx.x * blockDim.x + threadIdx.x;
    if (e < EE) {
        int s = ei[e];
        int d = ei[EE + e];
        int pos = atomicAdd(&g_cursor[d], 1);
        g_csrsrc[pos] = s;
    }
}

// ---------------- fused GCN layer 1 (linearity: Agg(x@W) == Agg(x)@W) ---------
__global__ __launch_bounds__(256) void k_gcn_l1(const float* __restrict__ x,
                                                const float* __restrict__ w1,
                                                const float* __restrict__ b1,
                                                __half* __restrict__ ah) {
    __shared__ float xb[3];
    int n = blockIdx.x;
    int tid = threadIdx.x;
    if (tid < 3) {
        float din = g_dinv[n];
        float acc = x[n * 3 + tid] * din * din;
        int s0 = g_rowstart[n], s1 = g_rowstart[n + 1];
        for (int j = s0; j < s1; j++) {
            int s = g_csrsrc[j];
            acc += x[s * 3 + tid] * g_dinv[s] * din;
        }
        xb[tid] = acc;
    }
    __syncthreads();
    float x0 = xb[0], x1 = xb[1], x2 = xb[2];
    size_t base = (size_t)n * HH;
#pragma unroll
    for (int c = 0; c < 3; c++) {
        int f = tid + c * 256;
        float v = x0 * w1[f] + x1 * w1[HH + f] + x2 * w1[2 * HH + f] + b1[f];
        ah[base + f] = __float2half(fmaxf(v, 0.f));
    }
}

// ---------------- weight transpose + convert (fp16) ----------------
__global__ void k_split_w(const float* __restrict__ w,
                          __half* __restrict__ th) {
    int idx = blockIdx.x * 256 + threadIdx.x;
    int n = idx / HH, k = idx % HH;
    th[idx] = __float2half(w[(size_t)k * HH + n]);
}

// ---------------- mma.sync GEMM: C[M,768] = A[M,768] @ W[768,768] --------------
// A fp16 [M,768]; W transposed fp16 [768(N),768(K)]. Single-pass, fp32 accum.
// 3-stage cp.async pipeline, wait_group 1. C written fp16.
#define GBM 128
#define GBN 128
#define GBK 32
#define KIT (HH / GBK)          // 24
#define TROW 40                 // padded row (fp16 elems): 80 bytes
#define TSZ (GBM * TROW)        // 5120 fp16 elems per tile
#define STGB (2 * TSZ * 2)      // 20480 bytes per stage: [A][Bh]
#define MMA_SMEM 61440          // 3 stages x 20480 (epilogue 128*136*2=34816 fits)

__device__ __forceinline__ void ldsm4(uint32_t* r, uint32_t addr) {
    asm volatile("ldmatrix.sync.aligned.m8n8.x4.shared.b16 {%0,%1,%2,%3}, [%4];"
                 : "=r"(r[0]), "=r"(r[1]), "=r"(r[2]), "=r"(r[3]) : "r"(addr));
}
__device__ __forceinline__ void mma16816(float* c, const uint32_t* a, uint32_t b0,
                                         uint32_t b1) {
    asm volatile(
        "mma.sync.aligned.m16n8k16.row.col.f32.f16.f16.f32 "
        "{%0,%1,%2,%3}, {%4,%5,%6,%7}, {%8,%9}, {%0,%1,%2,%3};"
        : "+f"(c[0]), "+f"(c[1]), "+f"(c[2]), "+f"(c[3])
        : "r"(a[0]), "r"(a[1]), "r"(a[2]), "r"(a[3]), "r"(b0), "r"(b1));
}
__device__ __forceinline__ void cpa16(uint32_t dst, const void* src, int sz) {
    asm volatile("cp.async.ca.shared.global [%0], [%1], 16, %2;"
                 :: "r"(dst), "l"(src), "r"(sz) : "memory");
}

__global__ __launch_bounds__(256) void k_mma_gemm(const __half* __restrict__ A,
                                                  const __half* __restrict__ Bh,
                                                  __half* __restrict__ C) {
    extern __shared__ char smem[];
    uint32_t sb;
    asm("{ .reg .u64 t; cvta.to.shared.u64 t, %1; cvt.u32.u64 %0, t; }"
        : "=r"(sb) : "l"(smem));
    int tid = threadIdx.x;
    int lane = tid & 31, wid = tid >> 5;
    int wm = wid & 1, wn = wid >> 1;
    int row0 = blockIdx.x * GBM;
    int col0 = blockIdx.y * GBN;

    float acc[4][4][4];
#pragma unroll
    for (int i = 0; i < 4; i++)
#pragma unroll
        for (int j = 0; j < 4; j++)
#pragma unroll
            for (int q = 0; q < 4; q++) acc[i][j][q] = 0.f;

    int vr = tid >> 2;          // row handled by this thread's vectors
    int vc = (tid & 3) * 8;     // fp16 col within 32-wide chunk
    int grA = row0 + vr;
    int okA = (grA < NN) ? 16 : 0;
    const char* pA0 = (const char*)(A + (size_t)(okA ? grA : 0) * HH + vc);
    const char* pBh0 = (const char*)(Bh + (size_t)(col0 + vr) * HH + vc);
    int grA2 = row0 + vr + 64;
    int okA2 = (grA2 < NN) ? 16 : 0;
    const char* pA1 = (const char*)(A + (size_t)(okA2 ? grA2 : 0) * HH + vc);
    const char* pBh1 = (const char*)(Bh + (size_t)(col0 + vr + 64) * HH + vc);
    uint32_t d0 = sb + (vr * TROW + vc) * 2;
    uint32_t d1 = sb + ((vr + 64) * TROW + vc) * 2;

#define LOAD_TILES(stg, kbyte)                                                  \
    do {                                                                        \
        uint32_t bo = (stg) * STGB;                                             \
        cpa16(bo + d0 + 0 * TSZ * 2, pA0 + (kbyte), okA);                       \
        cpa16(bo + d1 + 0 * TSZ * 2, pA1 + (kbyte), okA2);                      \
        cpa16(bo + d0 + 1 * TSZ * 2, pBh0 + (kbyte), 16);                       \
        cpa16(bo + d1 + 1 * TSZ * 2, pBh1 + (kbyte), 16);                       \
        asm volatile("cp.async.commit_group;" ::: "memory");                    \
    } while (0)

    LOAD_TILES(0, 0);
    LOAD_TILES(1, GBK * 2);

    int ar = lane & 15;
    int kc = (lane >> 4) * 8;

    for (int kt = 0; kt < KIT; kt++) {
        if (kt + 1 < KIT)
            asm volatile("cp.async.wait_group 1;" ::: "memory");
        else
            asm volatile("cp.async.wait_group 0;" ::: "memory");
        __syncthreads();
        if (kt + 2 < KIT) LOAD_TILES((kt + 2) % 3, (kt + 2) * GBK * 2);

        uint32_t tb = sb + (kt % 3) * STGB;
#pragma unroll
        for (int ks = 0; ks < 2; ks++) {
            int kb = ks * 16 + kc;
            uint32_t bh[2][4], af[4][4];
#pragma unroll
            for (int nb = 0; nb < 2; nb++)
                ldsm4(bh[nb],
                      tb + 1 * TSZ * 2 + ((wn * 32 + nb * 16 + ar) * TROW + kb) * 2);
#pragma unroll
            for (int mf = 0; mf < 4; mf++)
                ldsm4(af[mf], tb + ((wm * 64 + mf * 16 + ar) * TROW + kb) * 2);
#pragma unroll
            for (int mf = 0; mf < 4; mf++)
#pragma unroll
                for (int nb = 0; nb < 2; nb++)
#pragma unroll
                    for (int h = 0; h < 2; h++)
                        mma16816(acc[mf][nb * 2 + h], af[mf], bh[nb][h],
                                 bh[nb][h + 2]);
        }
    }
    __syncthreads();

    // epilogue: single-stage 128x136 fp16 smem, uint4 (8-half) stores
    __half* stage = (__half*)smem;
    {
        int r0r = wm * 64 + (lane >> 2);
        int c0c = wn * 32 + (lane & 3) * 2;
#pragma unroll
        for (int mf = 0; mf < 4; mf++)
#pragma unroll
            for (int nf = 0; nf < 4; nf++) {
                float* cc = acc[mf][nf];
                int rr = r0r + mf * 16;
                int ccol = c0c + nf * 8;
                stage[rr * 136 + ccol] = __float2half(cc[0]);
                stage[rr * 136 + ccol + 1] = __float2half(cc[1]);
                stage[(rr + 8) * 136 + ccol] = __float2half(cc[2]);
                stage[(rr + 8) * 136 + ccol + 1] = __float2half(cc[3]);
            }
    }
    __syncthreads();
#pragma unroll
    for (int j = 0; j < 8; j++) {
        int e = tid + 256 * j;
        int rr = e >> 4, c8 = e & 15;
        int gr = row0 + rr;
        if (gr < NN) {
            uint4 v = *(const uint4*)&stage[rr * 136 + c8 * 8];
            *(uint4*)&C[(size_t)gr * HH + col0 + c8 * 8] = v;
        }
    }
}

// ---------------- GCN aggregation (+bias+relu), half2 vectorized ---------------
__global__ __launch_bounds__(384) void k_gcn_agg_h(const __half* __restrict__ T,
                                                   __half* __restrict__ ah,
                                                   const float* __restrict__ bias) {
    int n = blockIdx.x;
    float din = g_dinv[n];
    int s0 = g_rowstart[n], s1 = g_rowstart[n + 1];
    int t = threadIdx.x;           // half2 index 0..383
    float selfw = din * din;
    const __half2* rn = (const __half2*)(T + (size_t)n * HH);
    float2 v = __half22float2(rn[t]);
    float a0 = v.x * selfw, a1 = v.y * selfw;
    for (int j = s0; j < s1; j++) {
        int s = g_csrsrc[j];
        float w = g_dinv[s] * din;
        float2 r = __half22float2(((const __half2*)(T + (size_t)s * HH))[t]);
        a0 += r.x * w;
        a1 += r.y * w;
    }
    a0 = fmaxf(a0 + bias[2 * t], 0.f);
    a1 = fmaxf(a1 + bias[2 * t + 1], 0.f);
    ((__half2*)(ah + (size_t)n * HH))[t] = __floats2half2_rn(a0, a1);
}

// ---------------- GAT alpha (per node, per head dot products), half2 ----------
__global__ void k_alpha(const __half* __restrict__ Hg, const float* __restrict__ a_src,
                        const float* __restrict__ a_dst) {
    int gwarp = (blockIdx.x * blockDim.x + threadIdx.x) >> 5;
    int lane = threadIdx.x & 31;
    if (gwarp >= NN * NHD) return;
    int n = gwarp / NHD, h = gwarp % NHD;
    const __half2* row = (const __half2*)(Hg + (size_t)n * HH + h * HDD);
    float2 v = __half22float2(row[lane]);
    float s = v.x * a_src[h * HDD + 2 * lane] + v.y * a_src[h * HDD + 2 * lane + 1];
    float d = v.x * a_dst[h * HDD + 2 * lane] + v.y * a_dst[h * HDD + 2 * lane + 1];
#pragma unroll
    for (int o = 16; o; o >>= 1) {
        s += __shfl_xor_sync(0xFFFFFFFFu, s, o);
        d += __shfl_xor_sync(0xFFFFFFFFu, d, o);
    }
    if (lane == 0) { g_as[gwarp] = s; g_ad[gwarp] = d; }
}

// ---------------- GAT aggregation (softmax weights in smem), half2 ------------
// mode 1: relu + write fp16 (feeds next GEMM). mode 0: fp32 out, no relu.
#define CH 20
__global__ __launch_bounds__(384) void k_gat_agg(const __half* __restrict__ Hg,
                                                 float* __restrict__ outf,
                                                 __half* __restrict__ ah,
                                                 const float* __restrict__ bias,
                                                 int mode) {
    __shared__ float sm[NHD], ssi[NHD], sself[NHD];
    __shared__ float swgt[CH][NHD];
    int n = blockIdx.x;
    int s0 = g_rowstart[n], s1 = g_rowstart[n + 1];
    int tid = threadIdx.x;

    if (tid < NHD) {
        float adn = g_ad[n * NHD + tid];
        float e_self = lrelu(g_as[n * NHD + tid] + adn);
        float m = e_self;
        for (int j = s0; j < s1; j++) {
            int s = g_csrsrc[j];
            float v = lrelu(g_as[s * NHD + tid] + adn);
            m = fmaxf(m, v);
        }
        float sum = __expf(e_self - m);
        for (int j = s0; j < s1; j++) {
            int s = g_csrsrc[j];
            sum += __expf(lrelu(g_as[s * NHD + tid] + adn) - m);
        }
        float inv = 1.0f / sum;
        sm[tid] = m;
        ssi[tid] = inv;
        sself[tid] = __expf(e_self - m) * inv;
    }
    __syncthreads();

    int t = tid;                 // half2 index 0..383 (features 2t, 2t+1)
    int h = t >> 5;              // head = (2t)/64
    const __half2* rn = (const __half2*)(Hg + (size_t)n * HH);
    float2 v = __half22float2(rn[t]);
    float ws = sself[h];
    float a0 = v.x * ws, a1 = v.y * ws;

    for (int j0 = s0; j0 < s1; j0 += CH) {
        int cnt = min(CH, s1 - j0);
        if (tid < cnt * NHD) {
            int jj = tid / NHD, hh = tid % NHD;
            int s = g_csrsrc[j0 + jj];
            swgt[jj][hh] =
                __expf(lrelu(g_as[s * NHD + hh] + g_ad[n * NHD + hh]) - sm[hh]) *
                ssi[hh];
        }
        __syncthreads();
        for (int jj = 0; jj < cnt; jj++) {
            int s = g_csrsrc[j0 + jj];
            float2 r = __half22float2(((const __half2*)(Hg + (size_t)s * HH))[t]);
            float w = swgt[jj][h];
            a0 += r.x * w;
            a1 += r.y * w;
        }
        __syncthreads();
    }

    a0 += bias[2 * t];
    a1 += bias[2 * t + 1];
    if (mode) {
        ((__half2*)(ah + (size_t)n * HH))[t] =
            __floats2half2_rn(fmaxf(a0, 0.f), fmaxf(a1, 0.f));
    } else {
        float* o = outf + (size_t)n * HH;
        o[2 * t] = a0;
        o[2 * t + 1] = a1;
    }
}

// ---------------- global mean pool (sorted batch, binary search ranges) --------
__device__ __forceinline__ int lower_bound_batch(const int* b, int key) {
    int lo = 0, hi = NN;
    while (lo < hi) {
        int mid = (lo + hi) >> 1;
        if (b[mid] < key) lo = mid + 1; else hi = mid;
    }
    return lo;
}

__global__ void k_pool(const float* __restrict__ X, const int* __restrict__ batch) {
    int g = blockIdx.x / 12;
    int chunk = blockIdx.x % 12;
    int lo = lower_bound_batch(batch, g);
    int hi = lower_bound_batch(batch, g + 1);
    int f = chunk * 64 + threadIdx.x;
    float s = 0.f;
    for (int i = lo; i < hi; i++) s += X[(size_t)i * HH + f];
    float c = (float)((hi - lo) > 0 ? (hi - lo) : 1);
    g_pool[g * HH + f] = s / c;
}

// ---------------- classifier MLP ----------------
__global__ void k_mlp1(const float* __restrict__ wc1, const float* __restrict__ bc1) {
    __shared__ float sg[HH];
    int g = blockIdx.x;
    for (int i = threadIdx.x; i < HH; i += H2) sg[i] = g_pool[g * HH + i];
    __syncthreads();
    float acc = bc1[threadIdx.x];
    for (int k = 0; k < HH; k++) acc += sg[k] * wc1[k * H2 + threadIdx.x];
    g_zmlp[g * H2 + threadIdx.x] = fmaxf(acc, 0.f);
}

__global__ void k_mlp2(const float* __restrict__ wc2, const float* __restrict__ bc2,
                       float* __restrict__ out) {
    __shared__ float sz[H2];
    int g = blockIdx.x;
    for (int i = threadIdx.x; i < H2; i += 64) sz[i] = g_zmlp[g * H2 + i];
    __syncthreads();
    if (threadIdx.x < NCL) {
        float acc = bc2[threadIdx.x];
        for (int k = 0; k < H2; k++) acc += sz[k] * wc2[k * NCL + threadIdx.x];
        out[g * NCL + threadIdx.x] = acc;
    }
}

// ---------------- launch ----------------
extern "C" void kernel_launch(void* const* d_in, const int* in_sizes, int n_in,
                              void* d_out, int out_size) {
    const float* x    = (const float*)d_in[0];
    const int*   ei   = (const int*)d_in[1];
    const int*   batc = (const int*)d_in[2];
    const float* w1   = (const float*)d_in[3];
    const float* b1   = (const float*)d_in[4];
    const float* w2   = (const float*)d_in[5];
    const float* b2   = (const float*)d_in[6];
    const float* w3   = (const float*)d_in[7];
    const float* b3   = (const float*)d_in[8];
    const float* wg1  = (const float*)d_in[9];
    const float* as1  = (const float*)d_in[10];
    const float* ad1  = (const float*)d_in[11];
    const float* bg1  = (const float*)d_in[12];
    const float* wg2  = (const float*)d_in[13];
    const float* as2  = (const float*)d_in[14];
    const float* ad2  = (const float*)d_in[15];
    const float* bg2  = (const float*)d_in[16];
    const float* wc1  = (const float*)d_in[17];
    const float* bc1  = (const float*)d_in[18];
    const float* wc2  = (const float*)d_in[19];
    const float* bc2  = (const float*)d_in[20];
    float* out = (float*)d_out;

    float* bufA;
    __half *bufB, *Ah, *W4;
    cudaGetSymbolAddress((void**)&bufA, g_bufA);
    cudaGetSymbolAddress((void**)&bufB, g_bufB);
    cudaGetSymbolAddress((void**)&Ah, g_Ah);
    cudaGetSymbolAddress((void**)&W4, g_W4);
    __half* Wt[4] = {W4, W4 + (size_t)HH * HH, W4 + 2 * (size_t)HH * HH,
                     W4 + 3 * (size_t)HH * HH};

    cudaFuncSetAttribute(k_mma_gemm, cudaFuncAttributeMaxDynamicSharedMemorySize,
                         MMA_SMEM);

    dim3 tc_grid((NN + GBM - 1) / GBM, HH / GBN);   // x = row
    int splitW_blocks = (HH * HH) / 256;

    // weight conversions up front (independent of activations)
    k_split_w<<<splitW_blocks, 256>>>(w2, Wt[0]);
    k_split_w<<<splitW_blocks, 256>>>(w3, Wt[1]);
    k_split_w<<<splitW_blocks, 256>>>(wg1, Wt[2]);
    k_split_w<<<splitW_blocks, 256>>>(wg2, Wt[3]);

    // CSR build
    k_zero_cnt<<<(NN + 255) / 256, 256>>>();
    k_count<<<(EE + 255) / 256, 256>>>(ei);
    k_scan<<<1, 1024>>>();
    k_dinv<<<(NN + 255) / 256, 256>>>();
    k_fill<<<(EE + 255) / 256, 256>>>(ei);

    // GCN layer 1 (fused via linearity): x -> Ah
    k_gcn_l1<<<NN, 256>>>(x, w1, b1, Ah);

    // GCN layer 2
    k_mma_gemm<<<tc_grid, 256, MMA_SMEM>>>(Ah, Wt[0], bufB);
    k_gcn_agg_h<<<NN, 384>>>(bufB, Ah, b2);

    // GCN layer 3
    k_mma_gemm<<<tc_grid, 256, MMA_SMEM>>>(Ah, Wt[1], bufB);
    k_gcn_agg_h<<<NN, 384>>>(bufB, Ah, b3);

    // GAT layer 1: gemm -> bufB (Hg) ; alpha ; agg -> Ah (relu)
    k_mma_gemm<<<tc_grid, 256, MMA_SMEM>>>(Ah, Wt[2], bufB);
    k_alpha<<<(NN * NHD * 32 + 255) / 256, 256>>>(bufB, as1, ad1);
    k_gat_agg<<<NN, 384>>>(bufB, nullptr, Ah, bg1, 1);

    // GAT layer 2: gemm -> bufB ; alpha ; agg -> bufA (fp32, no relu)
    k_mma_gemm<<<tc_grid, 256, MMA_SMEM>>>(Ah, Wt[3], bufB);
    k_alpha<<<(NN * NHD * 32 + 255) / 256, 256>>>(bufB, as2, ad2);
    k_gat_agg<<<NN, 384>>>(bufB, bufA, nullptr, bg2, 0);

    // pool + MLP
    k_pool<<<NGR * 12, 64>>>(bufA, batc);
    k_mlp1<<<NGR, H2>>>(wc1, bc1);
    k_mlp2<<<NGR, 64>>>(wc2, bc2, out);
}

// round 17
// speedup vs baseline: 1.0021x; 1.0021x over previous
#include <cuda_runtime.h>
#include <cuda_bf16.h>
#include <cuda_fp16.h>
#include <math.h>
#include <stdint.h>

#define NN 50000
#define EE 100000
#define HH 768
#define NHD 12
#define HDD 64
#define NGR 64
#define NCL 10
#define H2 384

// ---------------- scratch (static device globals; no allocation) ----------------
__device__ float g_bufA[(size_t)NN * HH];
__device__ __half g_bufB[(size_t)NN * HH];
__device__ __half g_Ah[(size_t)NN * HH];
__device__ __half g_W4[4][(size_t)HH * HH];   // transposed: [N=768][K=768]
__device__ float g_dinv[NN];
__device__ int   g_cnt[NN];
__device__ int   g_rowstart[NN + 1];
__device__ int   g_cursor[NN];
__device__ int   g_csrsrc[EE];
__device__ float g_as[NN * NHD];
__device__ float g_ad[NN * NHD];
__device__ float g_pool[NGR * HH];
__device__ float g_zmlp[NGR * H2];

__device__ __forceinline__ float lrelu(float x) { return x > 0.f ? x : 0.2f * x; }

// ---------------- CSR build ----------------
__global__ void k_zero_cnt() {
    int i = blockIdx.x * blockDim.x + threadIdx.x;
    if (i < NN) g_cnt[i] = 0;
}

__global__ void k_count(const int* __restrict__ ei) {
    int e = blockIdx.x * blockDim.x + threadIdx.x;
    if (e < EE) atomicAdd(&g_cnt[ei[EE + e]], 1);
}

__global__ void k_scan() {
    __shared__ int sh[1024];
    int tid = threadIdx.x;
    int off = 0;
    for (int base = 0; base < NN; base += 1024) {
        int i = base + tid;
        int v = (i < NN) ? g_cnt[i] : 0;
        sh[tid] = v;
        __syncthreads();
        for (int s = 1; s < 1024; s <<= 1) {
            int t = (tid >= s) ? sh[tid - s] : 0;
            __syncthreads();
            sh[tid] += t;
            __syncthreads();
        }
        if (i < NN) {
            int excl = off + sh[tid] - v;
            g_rowstart[i] = excl;
            g_cursor[i] = excl;
        }
        int tot = sh[1023];
        __syncthreads();
        off += tot;
    }
    if (tid == 0) g_rowstart[NN] = off;
}

__global__ void k_dinv() {
    int i = blockIdx.x * blockDim.x + threadIdx.x;
    if (i < NN) g_dinv[i] = rsqrtf((float)(g_cnt[i] + 1));
}

__global__ void k_fill(const int* __restrict__ ei) {
    int e = blockIdx.x * blockDim.x + threadIdx.x;
    if (e < EE) {
        int s = ei[e];
        int d = ei[EE + e];
        int pos = atomicAdd(&g_cursor[d], 1);
        g_csrsrc[pos] = s;
    }
}

// ---------------- fused GCN layer 1 (linearity: Agg(x@W) == Agg(x)@W) ---------
__global__ __launch_bounds__(256) void k_gcn_l1(const float* __restrict__ x,
                                                const float* __restrict__ w1,
                                                const float* __restrict__ b1,
                                                __half* __restrict__ ah) {
    __shared__ float xb[3];
    int n = blockIdx.x;
    int tid = threadIdx.x;
    if (tid < 3) {
        float din = g_dinv[n];
        float acc = x[n * 3 + tid] * din * din;
        int s0 = g_rowstart[n], s1 = g_rowstart[n + 1];
        for (int j = s0; j < s1; j++) {
            int s = g_csrsrc[j];
            acc += x[s * 3 + tid] * g_dinv[s] * din;
        }
        xb[tid] = acc;
    }
    __syncthreads();
    float x0 = xb[0], x1 = xb[1], x2 = xb[2];
    size_t base = (size_t)n * HH;
#pragma unroll
    for (int c = 0; c < 3; c++) {
        int f = tid + c * 256;
        float v = x0 * w1[f] + x1 * w1[HH + f] + x2 * w1[2 * HH + f] + b1[f];
        ah[base + f] = __float2half(fmaxf(v, 0.f));
    }
}

// ---------------- weight transpose + convert (fp16) ----------------
__global__ void k_split_w(const float* __restrict__ w,
                          __half* __restrict__ th) {
    int idx = blockIdx.x * 256 + threadIdx.x;
    int n = idx / HH, k = idx % HH;
    th[idx] = __float2half(w[(size_t)k * HH + n]);
}

// ---------------- mma.sync GEMM: C[M,768] = A[M,768] @ W[768,768] --------------
// A fp16 [M,768]; W transposed fp16 [768(N),768(K)]. Single-pass, fp32 accum.
// 2-stage double buffer (R14 configuration). C written fp16.
#define GBM 128
#define GBN 128
#define GBK 32
#define KIT (HH / GBK)          // 24
#define TROW 40                 // padded row (fp16 elems): 80 bytes
#define TSZ (GBM * TROW)        // 5120 fp16 elems per tile
#define STGB (2 * TSZ * 2)      // 20480 bytes per stage: [A][Bh]
#define MMA_SMEM 40960          // max(2*STGB=40960, epilogue 128*136*2=34816)

__device__ __forceinline__ void ldsm4(uint32_t* r, uint32_t addr) {
    asm volatile("ldmatrix.sync.aligned.m8n8.x4.shared.b16 {%0,%1,%2,%3}, [%4];"
                 : "=r"(r[0]), "=r"(r[1]), "=r"(r[2]), "=r"(r[3]) : "r"(addr));
}
__device__ __forceinline__ void mma16816(float* c, const uint32_t* a, uint32_t b0,
                                         uint32_t b1) {
    asm volatile(
        "mma.sync.aligned.m16n8k16.row.col.f32.f16.f16.f32 "
        "{%0,%1,%2,%3}, {%4,%5,%6,%7}, {%8,%9}, {%0,%1,%2,%3};"
        : "+f"(c[0]), "+f"(c[1]), "+f"(c[2]), "+f"(c[3])
        : "r"(a[0]), "r"(a[1]), "r"(a[2]), "r"(a[3]), "r"(b0), "r"(b1));
}
__device__ __forceinline__ void cpa16(uint32_t dst, const void* src, int sz) {
    asm volatile("cp.async.ca.shared.global [%0], [%1], 16, %2;"
                 :: "r"(dst), "l"(src), "r"(sz) : "memory");
}

__global__ __launch_bounds__(256) void k_mma_gemm(const __half* __restrict__ A,
                                                  const __half* __restrict__ Bh,
                                                  __half* __restrict__ C) {
    extern __shared__ char smem[];
    uint32_t sb;
    asm("{ .reg .u64 t; cvta.to.shared.u64 t, %1; cvt.u32.u64 %0, t; }"
        : "=r"(sb) : "l"(smem));
    int tid = threadIdx.x;
    int lane = tid & 31, wid = tid >> 5;
    int wm = wid & 1, wn = wid >> 1;
    int row0 = blockIdx.x * GBM;
    int col0 = blockIdx.y * GBN;

    float acc[4][4][4];
#pragma unroll
    for (int i = 0; i < 4; i++)
#pragma unroll
        for (int j = 0; j < 4; j++)
#pragma unroll
            for (int q = 0; q < 4; q++) acc[i][j][q] = 0.f;

    int vr = tid >> 2;          // row handled by this thread's vectors
    int vc = (tid & 3) * 8;     // fp16 col within 32-wide chunk
    int grA = row0 + vr;
    int okA = (grA < NN) ? 16 : 0;
    const char* pA0 = (const char*)(A + (size_t)(okA ? grA : 0) * HH + vc);
    const char* pBh0 = (const char*)(Bh + (size_t)(col0 + vr) * HH + vc);
    int grA2 = row0 + vr + 64;
    int okA2 = (grA2 < NN) ? 16 : 0;
    const char* pA1 = (const char*)(A + (size_t)(okA2 ? grA2 : 0) * HH + vc);
    const char* pBh1 = (const char*)(Bh + (size_t)(col0 + vr + 64) * HH + vc);
    uint32_t d0 = sb + (vr * TROW + vc) * 2;
    uint32_t d1 = sb + ((vr + 64) * TROW + vc) * 2;

#define LOAD_TILES(buf, kbyte)                                                  \
    do {                                                                        \
        uint32_t bo = (buf) * STGB;                                             \
        cpa16(bo + d0 + 0 * TSZ * 2, pA0 + (kbyte), okA);                       \
        cpa16(bo + d1 + 0 * TSZ * 2, pA1 + (kbyte), okA2);                      \
        cpa16(bo + d0 + 1 * TSZ * 2, pBh0 + (kbyte), 16);                       \
        cpa16(bo + d1 + 1 * TSZ * 2, pBh1 + (kbyte), 16);                       \
        asm volatile("cp.async.commit_group;" ::: "memory");                    \
    } while (0)

    LOAD_TILES(0, 0);

    int ar = lane & 15;
    int kc = (lane >> 4) * 8;

    for (int kt = 0; kt < KIT; kt++) {
        asm volatile("cp.async.wait_group 0;" ::: "memory");
        __syncthreads();
        if (kt + 1 < KIT) LOAD_TILES((kt + 1) & 1, (kt + 1) * GBK * 2);

        uint32_t tb = sb + (kt & 1) * STGB;
#pragma unroll
        for (int ks = 0; ks < 2; ks++) {
            int kb = ks * 16 + kc;
            uint32_t bh[2][4], af[4][4];
#pragma unroll
            for (int nb = 0; nb < 2; nb++)
                ldsm4(bh[nb],
                      tb + 1 * TSZ * 2 + ((wn * 32 + nb * 16 + ar) * TROW + kb) * 2);
#pragma unroll
            for (int mf = 0; mf < 4; mf++)
                ldsm4(af[mf], tb + ((wm * 64 + mf * 16 + ar) * TROW + kb) * 2);
#pragma unroll
            for (int mf = 0; mf < 4; mf++)
#pragma unroll
                for (int nb = 0; nb < 2; nb++)
#pragma unroll
                    for (int h = 0; h < 2; h++)
                        mma16816(acc[mf][nb * 2 + h], af[mf], bh[nb][h],
                                 bh[nb][h + 2]);
        }
    }
    __syncthreads();

    // epilogue: single-stage 128x136 fp16 smem, uint4 (8-half) stores
    __half* stage = (__half*)smem;
    {
        int r0r = wm * 64 + (lane >> 2);
        int c0c = wn * 32 + (lane & 3) * 2;
#pragma unroll
        for (int mf = 0; mf < 4; mf++)
#pragma unroll
            for (int nf = 0; nf < 4; nf++) {
                float* cc = acc[mf][nf];
                int rr = r0r + mf * 16;
                int ccol = c0c + nf * 8;
                stage[rr * 136 + ccol] = __float2half(cc[0]);
                stage[rr * 136 + ccol + 1] = __float2half(cc[1]);
                stage[(rr + 8) * 136 + ccol] = __float2half(cc[2]);
                stage[(rr + 8) * 136 + ccol + 1] = __float2half(cc[3]);
            }
    }
    __syncthreads();
#pragma unroll
    for (int j = 0; j < 8; j++) {
        int e = tid + 256 * j;
        int rr = e >> 4, c8 = e & 15;
        int gr = row0 + rr;
        if (gr < NN) {
            uint4 v = *(const uint4*)&stage[rr * 136 + c8 * 8];
            *(uint4*)&C[(size_t)gr * HH + col0 + c8 * 8] = v;
        }
    }
}

// ---------------- GCN aggregation (+bias+relu), half2 vectorized ---------------
__global__ __launch_bounds__(384) void k_gcn_agg_h(const __half* __restrict__ T,
                                                   __half* __restrict__ ah,
                                                   const float* __restrict__ bias) {
    int n = blockIdx.x;
    float din = g_dinv[n];
    int s0 = g_rowstart[n], s1 = g_rowstart[n + 1];
    int t = threadIdx.x;           // half2 index 0..383
    float selfw = din * din;
    const __half2* rn = (const __half2*)(T + (size_t)n * HH);
    float2 v = __half22float2(rn[t]);
    float a0 = v.x * selfw, a1 = v.y * selfw;
    for (int j = s0; j < s1; j++) {
        int s = g_csrsrc[j];
        float w = g_dinv[s] * din;
        float2 r = __half22float2(((const __half2*)(T + (size_t)s * HH))[t]);
        a0 += r.x * w;
        a1 += r.y * w;
    }
    a0 = fmaxf(a0 + bias[2 * t], 0.f);
    a1 = fmaxf(a1 + bias[2 * t + 1], 0.f);
    ((__half2*)(ah + (size_t)n * HH))[t] = __floats2half2_rn(a0, a1);
}

// ---------------- GAT alpha (per node, per head dot products), half2 ----------
__global__ void k_alpha(const __half* __restrict__ Hg, const float* __restrict__ a_src,
                        const float* __restrict__ a_dst) {
    int gwarp = (blockIdx.x * blockDim.x + threadIdx.x) >> 5;
    int lane = threadIdx.x & 31;
    if (gwarp >= NN * NHD) return;
    int n = gwarp / NHD, h = gwarp % NHD;
    const __half2* row = (const __half2*)(Hg + (size_t)n * HH + h * HDD);
    float2 v = __half22float2(row[lane]);
    float s = v.x * a_src[h * HDD + 2 * lane] + v.y * a_src[h * HDD + 2 * lane + 1];
    float d = v.x * a_dst[h * HDD + 2 * lane] + v.y * a_dst[h * HDD + 2 * lane + 1];
#pragma unroll
    for (int o = 16; o; o >>= 1) {
        s += __shfl_xor_sync(0xFFFFFFFFu, s, o);
        d += __shfl_xor_sync(0xFFFFFFFFu, d, o);
    }
    if (lane == 0) { g_as[gwarp] = s; g_ad[gwarp] = d; }
}

// ---------------- GAT aggregation (softmax weights in smem), half2 ------------
// mode 1: relu + write fp16 (feeds next GEMM). mode 0: fp32 out, no relu.
#define CH 20
__global__ __launch_bounds__(384) void k_gat_agg(const __half* __restrict__ Hg,
                                                 float* __restrict__ outf,
                                                 __half* __restrict__ ah,
                                                 const float* __restrict__ bias,
                                                 int mode) {
    __shared__ float sm[NHD], ssi[NHD], sself[NHD];
    __shared__ float swgt[CH][NHD];
    int n = blockIdx.x;
    int s0 = g_rowstart[n], s1 = g_rowstart[n + 1];
    int tid = threadIdx.x;

    if (tid < NHD) {
        float adn = g_ad[n * NHD + tid];
        float e_self = lrelu(g_as[n * NHD + tid] + adn);
        float m = e_self;
        for (int j = s0; j < s1; j++) {
            int s = g_csrsrc[j];
            float v = lrelu(g_as[s * NHD + tid] + adn);
            m = fmaxf(m, v);
        }
        float sum = __expf(e_self - m);
        for (int j = s0; j < s1; j++) {
            int s = g_csrsrc[j];
            sum += __expf(lrelu(g_as[s * NHD + tid] + adn) - m);
        }
        float inv = 1.0f / sum;
        sm[tid] = m;
        ssi[tid] = inv;
        sself[tid] = __expf(e_self - m) * inv;
    }
    __syncthreads();

    int t = tid;                 // half2 index 0..383 (features 2t, 2t+1)
    int h = t >> 5;              // head = (2t)/64
    const __half2* rn = (const __half2*)(Hg + (size_t)n * HH);
    float2 v = __half22float2(rn[t]);
    float ws = sself[h];
    float a0 = v.x * ws, a1 = v.y * ws;

    for (int j0 = s0; j0 < s1; j0 += CH) {
        int cnt = min(CH, s1 - j0);
        if (tid < cnt * NHD) {
            int jj = tid / NHD, hh = tid % NHD;
            int s = g_csrsrc[j0 + jj];
            swgt[jj][hh] =
                __expf(lrelu(g_as[s * NHD + hh] + g_ad[n * NHD + hh]) - sm[hh]) *
                ssi[hh];
        }
        __syncthreads();
        for (int jj = 0; jj < cnt; jj++) {
            int s = g_csrsrc[j0 + jj];
            float2 r = __half22float2(((const __half2*)(Hg + (size_t)s * HH))[t]);
            float w = swgt[jj][h];
            a0 += r.x * w;
            a1 += r.y * w;
        }
        __syncthreads();
    }

    a0 += bias[2 * t];
    a1 += bias[2 * t + 1];
    if (mode) {
        ((__half2*)(ah + (size_t)n * HH))[t] =
            __floats2half2_rn(fmaxf(a0, 0.f), fmaxf(a1, 0.f));
    } else {
        float* o = outf + (size_t)n * HH;
        o[2 * t] = a0;
        o[2 * t + 1] = a1;
    }
}

// ---------------- global mean pool (sorted batch, binary search ranges) --------
__device__ __forceinline__ int lower_bound_batch(const int* b, int key) {
    int lo = 0, hi = NN;
    while (lo < hi) {
        int mid = (lo + hi) >> 1;
        if (b[mid] < key) lo = mid + 1; else hi = mid;
    }
    return lo;
}

__global__ void k_pool(const float* __restrict__ X, const int* __restrict__ batch) {
    int g = blockIdx.x / 12;
    int chunk = blockIdx.x % 12;
    int lo = lower_bound_batch(batch, g);
    int hi = lower_bound_batch(batch, g + 1);
    int f = chunk * 64 + threadIdx.x;
    float s = 0.f;
    for (int i = lo; i < hi; i++) s += X[(size_t)i * HH + f];
    float c = (float)((hi - lo) > 0 ? (hi - lo) : 1);
    g_pool[g * HH + f] = s / c;
}

// ---------------- classifier MLP ----------------
__global__ void k_mlp1(const float* __restrict__ wc1, const float* __restrict__ bc1) {
    __shared__ float sg[HH];
    int g = blockIdx.x;
    for (int i = threadIdx.x; i < HH; i += H2) sg[i] = g_pool[g * HH + i];
    __syncthreads();
    float acc = bc1[threadIdx.x];
    for (int k = 0; k < HH; k++) acc += sg[k] * wc1[k * H2 + threadIdx.x];
    g_zmlp[g * H2 + threadIdx.x] = fmaxf(acc, 0.f);
}

__global__ void k_mlp2(const float* __restrict__ wc2, const float* __restrict__ bc2,
                       float* __restrict__ out) {
    __shared__ float sz[H2];
    int g = blockIdx.x;
    for (int i = threadIdx.x; i < H2; i += 64) sz[i] = g_zmlp[g * H2 + i];
    __syncthreads();
    if (threadIdx.x < NCL) {
        float acc = bc2[threadIdx.x];
        for (int k = 0; k < H2; k++) acc += sz[k] * wc2[k * NCL + threadIdx.x];
        out[g * NCL + threadIdx.x] = acc;
    }
}

// ---------------- launch ----------------
extern "C" void kernel_launch(void* const* d_in, const int* in_sizes, int n_in,
                              void* d_out, int out_size) {
    const float* x    = (const float*)d_in[0];
    const int*   ei   = (const int*)d_in[1];
    const int*   batc = (const int*)d_in[2];
    const float* w1   = (const float*)d_in[3];
    const float* b1   = (const float*)d_in[4];
    const float* w2   = (const float*)d_in[5];
    const float* b2   = (const float*)d_in[6];
    const float* w3   = (const float*)d_in[7];
    const float* b3   = (const float*)d_in[8];
    const float* wg1  = (const float*)d_in[9];
    const float* as1  = (const float*)d_in[10];
    const float* ad1  = (const float*)d_in[11];
    const float* bg1  = (const float*)d_in[12];
    const float* wg2  = (const float*)d_in[13];
    const float* as2  = (const float*)d_in[14];
    const float* ad2  = (const float*)d_in[15];
    const float* bg2  = (const float*)d_in[16];
    const float* wc1  = (const float*)d_in[17];
    const float* bc1  = (const float*)d_in[18];
    const float* wc2  = (const float*)d_in[19];
    const float* bc2  = (const float*)d_in[20];
    float* out = (float*)d_out;

    float* bufA;
    __half *bufB, *Ah, *W4;
    cudaGetSymbolAddress((void**)&bufA, g_bufA);
    cudaGetSymbolAddress((void**)&bufB, g_bufB);
    cudaGetSymbolAddress((void**)&Ah, g_Ah);
    cudaGetSymbolAddress((void**)&W4, g_W4);
    __half* Wt[4] = {W4, W4 + (size_t)HH * HH, W4 + 2 * (size_t)HH * HH,
                     W4 + 3 * (size_t)HH * HH};

    cudaFuncSetAttribute(k_mma_gemm, cudaFuncAttributeMaxDynamicSharedMemorySize,
                         MMA_SMEM);

    dim3 tc_grid((NN + GBM - 1) / GBM, HH / GBN);   // x = row
    int splitW_blocks = (HH * HH) / 256;

    // weight conversions up front (independent of activations)
    k_split_w<<<splitW_blocks, 256>>>(w2, Wt[0]);
    k_split_w<<<splitW_blocks, 256>>>(w3, Wt[1]);
    k_split_w<<<splitW_blocks, 256>>>(wg1, Wt[2]);
    k_split_w<<<splitW_blocks, 256>>>(wg2, Wt[3]);

    // CSR build
    k_zero_cnt<<<(NN + 255) / 256, 256>>>();
    k_count<<<(EE + 255) / 256, 256>>>(ei);
    k_scan<<<1, 1024>>>();
    k_dinv<<<(NN + 255) / 256, 256>>>();
    k_fill<<<(EE + 255) / 256, 256>>>(ei);

    // GCN layer 1 (fused via linearity): x -> Ah
    k_gcn_l1<<<NN, 256>>>(x, w1, b1, Ah);

    // GCN layer 2
    k_mma_gemm<<<tc_grid, 256, MMA_SMEM>>>(Ah, Wt[0], bufB);
    k_gcn_agg_h<<<NN, 384>>>(bufB, Ah, b2);

    // GCN layer 3
    k_mma_gemm<<<tc_grid, 256, MMA_SMEM>>>(Ah, Wt[1], bufB);
    k_gcn_agg_h<<<NN, 384>>>(bufB, Ah, b3);

    // GAT layer 1: gemm -> bufB (Hg) ; alpha ; agg -> Ah (relu)
    k_mma_gemm<<<tc_grid, 256, MMA_SMEM>>>(Ah, Wt[2], bufB);
    k_alpha<<<(NN * NHD * 32 + 255) / 256, 256>>>(bufB, as1, ad1);
    k_gat_agg<<<NN, 384>>>(bufB, nullptr, Ah, bg1, 1);

    // GAT layer 2: gemm -> bufB ; alpha ; agg -> bufA (fp32, no relu)
    k_mma_gemm<<<tc_grid, 256, MMA_SMEM>>>(Ah, Wt[3], bufB);
    k_alpha<<<(NN * NHD * 32 + 255) / 256, 256>>>(bufB, as2, ad2);
    k_gat_agg<<<NN, 384>>>(bufB, bufA, nullptr, bg2, 0);

    // pool + MLP
    k_pool<<<NGR * 12, 64>>>(bufA, batc);
    k_mlp1<<<NGR, H2>>>(wc1, bc1);
    k_mlp2<<<NGR, 64>>>(wc2, bc2, out);
}